// round 4
// baseline (speedup 1.0000x reference)
#include <cuda_runtime.h>
#include <cstdint>

#define N_INP   64
#define N_HID   512
#define BATCH   128
#define SEQ     1024
#define DT_C    0.042f
#define CSZ     8      // cluster size (CTAs per cluster)
#define BC      8      // batches per cluster
#define HS      64     // hidden slice per CTA
#define THREADS 256
#define HYF_PITCH 520  // padded row pitch for hy_full (stays 16B aligned)

struct __align__(16) Smem {
    float4 W[512 * 16];          // h2h[:, slice], swizzled: W[k*16 + (g ^ (k&15))]
    float4 X2H[64 * 16];         // x2h[:, slice], swizzled likewise
    float  hy_full[BC * HYF_PITCH]; // replicated full hy per batch
    float  wrecv[CSZ * BC * HS]; // partial w from each peer: [src][b][k']
    float  hy_s[BC * HS];        // owned hy slice
    float  hz_s[BC * HS];        // owned hz slice
    float4 rec4[BC * 16];        // rec[b][slice]
    float4 i2h4[BC * 16];        // tanh(x@x2h)[b][slice]
    float  xs[BC * N_INP];       // x[b, t, :]
    float  biasS[HS], gammaS[HS], epsS[HS];
    float4 scratch[THREADS];     // pass1 k-split partials
};

__device__ __forceinline__ uint32_t smem_u32(const void* p) {
    uint32_t a;
    asm("{ .reg .u64 t; cvta.to.shared.u64 t, %1; cvt.u32.u64 %0, t; }"
        : "=r"(a) : "l"(p));
    return a;
}
__device__ __forceinline__ uint32_t mapa_u32(uint32_t a, uint32_t r) {
    uint32_t d;
    asm("mapa.shared::cluster.u32 %0, %1, %2;" : "=r"(d) : "r"(a), "r"(r));
    return d;
}
__device__ __forceinline__ void st_cluster_f32(uint32_t a, float v) {
    asm volatile("st.shared::cluster.f32 [%0], %1;" :: "r"(a), "f"(v) : "memory");
}
__device__ __forceinline__ uint32_t ctarank() {
    uint32_t r;
    asm("mov.u32 %0, %%cluster_ctarank;" : "=r"(r));
    return r;
}
#define CLUSTER_SYNC() do { \
    asm volatile("barrier.cluster.arrive.aligned;" ::: "memory"); \
    asm volatile("barrier.cluster.wait.aligned;" ::: "memory"); \
} while (0)

__global__ void __launch_bounds__(THREADS, 1) __cluster_dims__(CSZ, 1, 1)
piron_kernel(const float* __restrict__ x,
             const float* __restrict__ x2h,
             const float* __restrict__ h2h,
             const float* __restrict__ bias,
             const float* __restrict__ gamma,
             const float* __restrict__ eps,
             float* __restrict__ out,
             int out_size)
{
    extern __shared__ Smem smem[];
    Smem& S = smem[0];
    const int      t       = threadIdx.x;
    const uint32_t rank    = ctarank();
    const int      cluster = blockIdx.x / CSZ;
    const int      h0      = (int)rank * HS;

    // ---------------- init: load weights (swizzled), zero state ----------------
    for (int idx = t; idx < 512 * 16; idx += THREADS) {
        int k = idx >> 4, g = idx & 15;
        float4 v = *reinterpret_cast<const float4*>(h2h + (size_t)k * N_HID + h0 + g * 4);
        S.W[(k << 4) | (g ^ (k & 15))] = v;
    }
    for (int idx = t; idx < 64 * 16; idx += THREADS) {
        int i = idx >> 4, g = idx & 15;
        float4 v = *reinterpret_cast<const float4*>(x2h + (size_t)i * N_HID + h0 + g * 4);
        S.X2H[(i << 4) | (g ^ (i & 15))] = v;
    }
    if (t < HS) {
        S.biasS[t]  = bias[h0 + t];
        S.gammaS[t] = gamma[h0 + t];
        S.epsS[t]   = eps[h0 + t];
    }
    for (int idx = t; idx < BC * HS; idx += THREADS) { S.hy_s[idx] = 0.f; S.hz_s[idx] = 0.f; }
    for (int idx = t; idx < BC * HYF_PITCH; idx += THREADS) S.hy_full[idx] = 0.f;
    __syncthreads();
    CLUSTER_SYNC();

    // Base shared addresses (local); remote variants computed via mapa per store.
    const uint32_t my_wrecv_row = smem_u32(&S.wrecv[rank * BC * HS]); // peers index by MY rank
    const uint32_t my_hyfull    = smem_u32(&S.hy_full[0]);

    // thread roles
    const int g         = t & 15;        // float4 group within 64-wide slice
    const int bb        = (t >> 4) & 7;  // batch for pass1
    const int ks        = t >> 7;        // k-split half for pass1 / i2h duty
    const int lane      = t & 31;
    const int b_of_warp = t >> 5;        // batch for pass2 (8 warps = 8 batches)

    for (int step = 0; step < SEQ; ++step) {
        // ---- load x[b, step, :] for this cluster's 8 batches ----
        #pragma unroll
        for (int r = 0; r < 2; ++r) {
            int e = t + r * THREADS;          // 0..511
            int b = e >> 6, i = e & 63;
            S.xs[e] = x[(((size_t)(cluster * BC + b)) * SEQ + step) * N_INP + i];
        }
        __syncthreads();

        // ---- pass1: partial rec-dot over half of k (both thread halves) ----
        float4 acc = make_float4(0.f, 0.f, 0.f, 0.f);
        {
            const float* hyrow = &S.hy_full[bb * HYF_PITCH];
            const int kbase = ks * 256;
            #pragma unroll 1
            for (int kt = 0; kt < 256; kt += 16) {
                int k0 = kbase + kt;
                #pragma unroll
                for (int jj = 0; jj < 4; ++jj) {
                    float4 hv = *reinterpret_cast<const float4*>(&hyrow[k0 + jj * 4]);
                    float4 w0 = S.W[((k0 + jj * 4 + 0) << 4) | (g ^ (jj * 4 + 0))];
                    float4 w1 = S.W[((k0 + jj * 4 + 1) << 4) | (g ^ (jj * 4 + 1))];
                    float4 w2 = S.W[((k0 + jj * 4 + 2) << 4) | (g ^ (jj * 4 + 2))];
                    float4 w3 = S.W[((k0 + jj * 4 + 3) << 4) | (g ^ (jj * 4 + 3))];
                    acc.x = fmaf(w0.x, hv.x, acc.x); acc.y = fmaf(w0.y, hv.x, acc.y);
                    acc.z = fmaf(w0.z, hv.x, acc.z); acc.w = fmaf(w0.w, hv.x, acc.w);
                    acc.x = fmaf(w1.x, hv.y, acc.x); acc.y = fmaf(w1.y, hv.y, acc.y);
                    acc.z = fmaf(w1.z, hv.y, acc.z); acc.w = fmaf(w1.w, hv.y, acc.w);
                    acc.x = fmaf(w2.x, hv.z, acc.x); acc.y = fmaf(w2.y, hv.z, acc.y);
                    acc.z = fmaf(w2.z, hv.z, acc.z); acc.w = fmaf(w2.w, hv.z, acc.w);
                    acc.x = fmaf(w3.x, hv.w, acc.x); acc.y = fmaf(w3.y, hv.w, acc.y);
                    acc.z = fmaf(w3.z, hv.w, acc.z); acc.w = fmaf(w3.w, hv.w, acc.w);
                }
            }
        }
        S.scratch[t] = acc;

        // ks==1 half also computes i2h = tanh(x @ x2h) for its (b, g)
        if (ks) {
            float4 a2 = make_float4(0.f, 0.f, 0.f, 0.f);
            const float* xrow = &S.xs[bb * N_INP];
            #pragma unroll
            for (int i = 0; i < 64; ++i) {
                float4 w = S.X2H[(i << 4) | (g ^ (i & 15))];
                float xv = xrow[i];
                a2.x = fmaf(w.x, xv, a2.x); a2.y = fmaf(w.y, xv, a2.y);
                a2.z = fmaf(w.z, xv, a2.z); a2.w = fmaf(w.w, xv, a2.w);
            }
            a2.x = tanhf(a2.x); a2.y = tanhf(a2.y);
            a2.z = tanhf(a2.z); a2.w = tanhf(a2.w);
            S.i2h4[bb * 16 + g] = a2;
        }
        __syncthreads();

        if (!ks) {  // reduce the two k-halves, add bias, tanh -> rec
            float4 o = S.scratch[t + 128];
            float4 r;
            r.x = tanhf(acc.x + o.x + S.biasS[g * 4 + 0]);
            r.y = tanhf(acc.y + o.y + S.biasS[g * 4 + 1]);
            r.z = tanhf(acc.z + o.z + S.biasS[g * 4 + 2]);
            r.w = tanhf(acc.w + o.w + S.biasS[g * 4 + 3]);
            S.rec4[bb * 16 + g] = r;
        }
        __syncthreads();

        // ---- pass2: this CTA's h-slice partial of w[b][k] for ALL k; scatter to owners ----
        {
            const float4* recb = &S.rec4[b_of_warp * 16];
            #pragma unroll 1
            for (int ii = 0; ii < 16; ++ii) {
                int k  = lane + (ii << 5);
                int kb = k & 15;
                float4 a = make_float4(0.f, 0.f, 0.f, 0.f);
                const float4* wrow = &S.W[k << 4];
                #pragma unroll
                for (int gg = 0; gg < 16; ++gg) {
                    float4 w = wrow[gg ^ kb];
                    float4 r = recb[gg];
                    a.x = fmaf(w.x, r.x, a.x); a.y = fmaf(w.y, r.y, a.y);
                    a.z = fmaf(w.z, r.z, a.z); a.w = fmaf(w.w, r.w, a.w);
                }
                float wsum = (a.x + a.y) + (a.z + a.w);
                uint32_t peer = (uint32_t)(k >> 6);
                int      kin  = k & 63;
                uint32_t raddr = mapa_u32(
                    my_wrecv_row + (uint32_t)((b_of_warp * HS + kin) * 4), peer);
                st_cluster_f32(raddr, wsum);
            }
        }
        CLUSTER_SYNC();  // release pass2 scatters / acquire for the reduce

        // ---- reduce partials, update state, emit output, all-gather hy ----
        #pragma unroll
        for (int r = 0; r < 2; ++r) {
            int idx = t + r * THREADS;   // 0..511 => (b, kk)
            int b = idx >> 6, kk = idx & 63;
            float w = 0.f;
            #pragma unroll
            for (int j = 0; j < CSZ; ++j) w += S.wrecv[(j * BC + b) * HS + kk];
            float hy = S.hy_s[idx];
            float hz = S.hz_s[idx];
            float i2 = reinterpret_cast<const float*>(S.i2h4)[idx]; // b*64 + kk
            hz += DT_C * (i2 - w - S.gammaS[kk] * hy - S.epsS[kk] * hz);
            hy += DT_C * hz;
            S.hy_s[idx] = hy;
            S.hz_s[idx] = hz;
            out[(((size_t)(cluster * BC + b)) * SEQ + step) * N_HID + h0 + kk] = hy;
            // broadcast new hy slice element into every CTA's hy_full (incl. self)
            uint32_t loc = my_hyfull + (uint32_t)((b * HYF_PITCH + h0 + kk) * 4);
            #pragma unroll
            for (uint32_t p = 0; p < CSZ; ++p)
                st_cluster_f32(mapa_u32(loc, p), hy);
        }
        CLUSTER_SYNC();  // hy_full consistent before next step's pass1
    }

    // ---- final hy (second output, concatenated after states) ----
    if (out_size >= BATCH * SEQ * N_HID + BATCH * N_HID) {
        #pragma unroll
        for (int r = 0; r < 2; ++r) {
            int idx = t + r * THREADS;
            int b = idx >> 6, kk = idx & 63;
            out[(size_t)BATCH * SEQ * N_HID +
                (size_t)(cluster * BC + b) * N_HID + h0 + kk] = S.hy_s[idx];
        }
    }
}

extern "C" void kernel_launch(void* const* d_in, const int* in_sizes, int n_in,
                              void* d_out, int out_size) {
    const float* x     = (const float*)d_in[0];
    const float* x2h   = (const float*)d_in[1];
    const float* h2h   = (const float*)d_in[2];
    const float* bias  = (const float*)d_in[3];
    const float* gamma = (const float*)d_in[4];
    const float* eps   = (const float*)d_in[5];

    cudaFuncSetAttribute(piron_kernel,
                         cudaFuncAttributeMaxDynamicSharedMemorySize,
                         (int)sizeof(Smem));

    dim3 grid((BATCH / BC) * CSZ);   // 128 CTAs = 16 clusters of 8
    dim3 block(THREADS);
    piron_kernel<<<grid, block, sizeof(Smem)>>>(x, x2h, h2h, bias, gamma, eps,
                                                (float*)d_out, out_size);
}

// round 5
// speedup vs baseline: 1.8417x; 1.8417x over previous
#include <cuda_runtime.h>
#include <cstdint>

typedef unsigned long long u64;

#define N_INP   64
#define N_HID   512
#define BATCH   128
#define SEQ     1024
#define DT_C    0.042f
#define CSZ     8
#define BC      8
#define HS      64
#define THREADS 256
#define HYF_PITCH 516   // 516*4B row pitch: 16B-aligned, bank-staggered

struct __align__(16) Smem {
    float4 W[512 * 16];            // 128KB h2h[:,slice], slot = g ^ ((k>>2)&15)
    float  hyD[512 * 16];          // 32KB  (k,b) -> dup pair at [k*16 + b*2]
    float  hy_full[BC * HYF_PITCH];// 16.1KB all-gathered hy, [b][k]
    float  wrecv[CSZ * BC * HS];   // 16KB  [src][b][kin]
    float4 scratch[4 * 8 * 16];    // 8KB   pass1 partials [ks][b][g]
    float4 rec4[BC * 16];          // 2KB   rec[b][slice]
    float  i2h[BC * HS];           // 2KB   prefetched tanh(x@x2h) slice
    float  hy_s[BC * HS];          // owned hy slice
    float  hz_s[BC * HS];          // owned hz slice
    float  biasS[HS], gammaS[HS], epsS[HS];
};

__device__ __forceinline__ uint32_t smem_u32(const void* p) {
    uint32_t a;
    asm("{ .reg .u64 t; cvta.to.shared.u64 t, %1; cvt.u32.u64 %0, t; }"
        : "=r"(a) : "l"(p));
    return a;
}
__device__ __forceinline__ uint32_t mapa_u32(uint32_t a, uint32_t r) {
    uint32_t d;
    asm("mapa.shared::cluster.u32 %0, %1, %2;" : "=r"(d) : "r"(a), "r"(r));
    return d;
}
__device__ __forceinline__ void st_cluster_v4(uint32_t a, float4 v) {
    asm volatile("st.shared::cluster.v4.f32 [%0], {%1, %2, %3, %4};"
                 :: "r"(a), "f"(v.x), "f"(v.y), "f"(v.z), "f"(v.w) : "memory");
}
__device__ __forceinline__ uint32_t ctarank() {
    uint32_t r;
    asm("mov.u32 %0, %%cluster_ctarank;" : "=r"(r));
    return r;
}
__device__ __forceinline__ void fma2(u64& d, u64 a, u64 b) {
    asm("fma.rn.f32x2 %0, %1, %2, %0;" : "+l"(d) : "l"(a), "l"(b));
}
__device__ __forceinline__ float2 unpk(u64 v) {
    float2 f;
    asm("mov.b64 {%0, %1}, %2;" : "=f"(f.x), "=f"(f.y) : "l"(v));
    return f;
}
#define CLUSTER_SYNC() do { \
    asm volatile("barrier.cluster.arrive.aligned;" ::: "memory"); \
    asm volatile("barrier.cluster.wait.aligned;" ::: "memory"); \
} while (0)

// ===================== prelude: i2h_all = tanh(x @ x2h) -> out ==============
#define PRE_CTAS 512
__global__ void __launch_bounds__(256, 1)
i2h_kernel(const float* __restrict__ x, const float* __restrict__ x2h,
           float* __restrict__ out)
{
    extern __shared__ float ps[];
    float* W2 = ps;                 // 64*512 floats (128KB)
    float* xd = ps + 64 * 512;      // 8 rows dup'd: 8*64*2 floats (4KB)
    const int t = threadIdx.x;

    for (int idx = t; idx < 64 * 512 / 4; idx += 256)
        *reinterpret_cast<float4*>(&W2[idx * 4]) =
            *reinterpret_cast<const float4*>(&x2h[idx * 4]);

    const int hg = t & 63, rp = t >> 6;
    const long r0 = (long)blockIdx.x * 256;

    for (int tile = 0; tile < 32; ++tile) {
        __syncthreads();
        #pragma unroll
        for (int rr = 0; rr < 2; ++rr) {
            int e = t + rr * 256;
            int row = e >> 6, i = e & 63;
            float v = x[(r0 + tile * 8 + row) * 64 + i];
            *reinterpret_cast<float2*>(&xd[e * 2]) = make_float2(v, v);
        }
        __syncthreads();

        u64 acc[2][4];
        #pragma unroll
        for (int a = 0; a < 2; ++a)
            #pragma unroll
            for (int b = 0; b < 4; ++b) acc[a][b] = 0ull;

        const int roff = (rp * 2) * 128;
        #pragma unroll 4
        for (int i = 0; i < 64; ++i) {
            ulonglong2 wA = *reinterpret_cast<const ulonglong2*>(&W2[i * 512 + hg * 8]);
            ulonglong2 wB = *reinterpret_cast<const ulonglong2*>(&W2[i * 512 + hg * 8 + 4]);
            u64 xe = *reinterpret_cast<const u64*>(&xd[roff + i * 2]);
            u64 xo = *reinterpret_cast<const u64*>(&xd[roff + 128 + i * 2]);
            fma2(acc[0][0], wA.x, xe); fma2(acc[0][1], wA.y, xe);
            fma2(acc[0][2], wB.x, xe); fma2(acc[0][3], wB.y, xe);
            fma2(acc[1][0], wA.x, xo); fma2(acc[1][1], wA.y, xo);
            fma2(acc[1][2], wB.x, xo); fma2(acc[1][3], wB.y, xo);
        }
        #pragma unroll
        for (int rr = 0; rr < 2; ++rr) {
            long row = r0 + tile * 8 + rp * 2 + rr;
            float4 o0, o1; float2 f;
            f = unpk(acc[rr][0]); o0.x = tanhf(f.x); o0.y = tanhf(f.y);
            f = unpk(acc[rr][1]); o0.z = tanhf(f.x); o0.w = tanhf(f.y);
            f = unpk(acc[rr][2]); o1.x = tanhf(f.x); o1.y = tanhf(f.y);
            f = unpk(acc[rr][3]); o1.z = tanhf(f.x); o1.w = tanhf(f.y);
            *reinterpret_cast<float4*>(&out[row * 512 + hg * 8])     = o0;
            *reinterpret_cast<float4*>(&out[row * 512 + hg * 8 + 4]) = o1;
        }
    }
}

// ===================== main recurrence =====================================
__global__ void __launch_bounds__(THREADS, 1) __cluster_dims__(CSZ, 1, 1)
piron_kernel(const float* __restrict__ h2h,
             const float* __restrict__ bias,
             const float* __restrict__ gamma,
             const float* __restrict__ eps,
             float* outp,
             int out_size)
{
    extern __shared__ Smem smem[];
    Smem& S = smem[0];
    const int      t       = threadIdx.x;
    const uint32_t rank    = ctarank();
    const int      cluster = blockIdx.x / CSZ;
    const int      h0      = (int)rank * HS;

    // ---- init: W (swizzled), consts, zero state ----
    for (int idx = t; idx < 512 * 16; idx += THREADS) {
        int k = idx >> 4, g = idx & 15;
        float4 v = *reinterpret_cast<const float4*>(h2h + (size_t)k * N_HID + h0 + g * 4);
        S.W[(k << 4) | (g ^ ((k >> 2) & 15))] = v;
    }
    if (t < HS) {
        S.biasS[t]  = bias[h0 + t];
        S.gammaS[t] = gamma[h0 + t];
        S.epsS[t]   = eps[h0 + t];
    }
    for (int idx = t; idx < BC * HS; idx += THREADS) { S.hy_s[idx] = 0.f; S.hz_s[idx] = 0.f; }
    for (int idx = t; idx < BC * HYF_PITCH; idx += THREADS) S.hy_full[idx] = 0.f;
    __syncthreads();
    CLUSTER_SYNC();

    // ---- fixed thread roles / precomputed DSMEM addresses ----
    // pass1: (g, ks, bq)
    const int g      = t & 15;
    const int c16    = t >> 4;
    const int ks     = c16 >> 2;       // 0..3  k-split
    const int bq     = c16 & 3;        // 0..3  batch pair
    const int kbase1 = ks * 128;
    // pass2: (k4, bh)
    const int      k4     = t & 127;
    const int      bh     = t >> 7;
    const int      swz2   = k4 & 15;
    const int      kbase2 = k4 * 4;
    const uint32_t peer2  = (uint32_t)(k4 >> 4);
    const int      kin0   = (k4 & 15) * 4;
    uint32_t wr_addr[4];
    #pragma unroll
    for (int bb = 0; bb < 4; ++bb)
        wr_addr[bb] = mapa_u32(
            smem_u32(&S.wrecv[((int)rank * BC + bh * 4 + bb) * HS + kin0]), peer2);
    // update: (ub, uq), t < 128
    const int ub = (t >> 4) & 7;
    const int uq = t & 15;
    uint32_t hyb_addr[CSZ];
    {
        uint32_t loc = smem_u32(&S.hy_full[ub * HYF_PITCH + h0 + uq * 4]);
        #pragma unroll
        for (uint32_t p = 0; p < CSZ; ++p) hyb_addr[p] = mapa_u32(loc, p);
    }
    // transpose: (tb, tkb)
    const int tb  = t & 7;
    const int tkb = t >> 3;

    for (int step = 0; step < SEQ; ++step) {
        // ---- A: transpose hy_full -> hyD (dup pairs) ----
        {
            int kk0 = tkb * 16;
            #pragma unroll
            for (int j = 0; j < 4; ++j) {
                float4 v = *reinterpret_cast<const float4*>(
                    &S.hy_full[tb * HYF_PITCH + kk0 + j * 4]);
                int k = kk0 + j * 4;
                *reinterpret_cast<float2*>(&S.hyD[(k + 0) * 16 + tb * 2]) = make_float2(v.x, v.x);
                *reinterpret_cast<float2*>(&S.hyD[(k + 1) * 16 + tb * 2]) = make_float2(v.y, v.y);
                *reinterpret_cast<float2*>(&S.hyD[(k + 2) * 16 + tb * 2]) = make_float2(v.z, v.z);
                *reinterpret_cast<float2*>(&S.hyD[(k + 3) * 16 + tb * 2]) = make_float2(v.w, v.w);
            }
        }
        __syncthreads();

        // ---- B: pass1 rec-partials (packed), + i2h prefetch on t<128 ----
        float4 i2v;
        if (t < 128)
            i2v = *reinterpret_cast<const float4*>(
                outp + (((size_t)(cluster * BC + ub)) * SEQ + step) * N_HID + h0 + uq * 4);

        u64 a00 = 0, a01 = 0, a10 = 0, a11 = 0;
        #pragma unroll 4
        for (int j = 0; j < 128; ++j) {
            int k = kbase1 + j;
            int slot = g ^ ((j >> 2) & 15);
            ulonglong2 w2 = *reinterpret_cast<const ulonglong2*>(&S.W[(k << 4) + slot]);
            ulonglong2 h2 = *reinterpret_cast<const ulonglong2*>(&S.hyD[(k << 4) + bq * 4]);
            fma2(a00, w2.x, h2.x); fma2(a01, w2.y, h2.x);
            fma2(a10, w2.x, h2.y); fma2(a11, w2.y, h2.y);
        }
        {
            ulonglong2 s0; s0.x = a00; s0.y = a01;
            ulonglong2 s1; s1.x = a10; s1.y = a11;
            *reinterpret_cast<ulonglong2*>(&S.scratch[(ks * 8 + bq * 2 + 0) * 16 + g]) = s0;
            *reinterpret_cast<ulonglong2*>(&S.scratch[(ks * 8 + bq * 2 + 1) * 16 + g]) = s1;
        }
        if (t < 128)
            *reinterpret_cast<float4*>(&S.i2h[ub * HS + uq * 4]) = i2v;
        __syncthreads();

        // ---- C: reduce k-splits + bias + tanh -> rec4 ----
        if (t < 128) {
            float4 v = S.scratch[(0 * 8 + ub) * 16 + uq];
            #pragma unroll
            for (int s = 1; s < 4; ++s) {
                float4 u = S.scratch[(s * 8 + ub) * 16 + uq];
                v.x += u.x; v.y += u.y; v.z += u.z; v.w += u.w;
            }
            float4 bi = *reinterpret_cast<const float4*>(&S.biasS[uq * 4]);
            float4 r;
            r.x = tanhf(v.x + bi.x); r.y = tanhf(v.y + bi.y);
            r.z = tanhf(v.z + bi.z); r.w = tanhf(v.w + bi.w);
            S.rec4[ub * 16 + uq] = r;
        }
        __syncthreads();

        // ---- D: pass2 w = rec @ Wslice^T (packed over h), scatter v4 ----
        {
            u64 ww[16];
            #pragma unroll
            for (int q = 0; q < 16; ++q) ww[q] = 0ull;
            #pragma unroll 4
            for (int gg = 0; gg < 16; ++gg) {
                int slot = gg ^ swz2;
                ulonglong2 w0 = *reinterpret_cast<const ulonglong2*>(&S.W[(kbase2 + 0) * 16 + slot]);
                ulonglong2 w1 = *reinterpret_cast<const ulonglong2*>(&S.W[(kbase2 + 1) * 16 + slot]);
                ulonglong2 w2 = *reinterpret_cast<const ulonglong2*>(&S.W[(kbase2 + 2) * 16 + slot]);
                ulonglong2 w3 = *reinterpret_cast<const ulonglong2*>(&S.W[(kbase2 + 3) * 16 + slot]);
                #pragma unroll
                for (int bb = 0; bb < 4; ++bb) {
                    ulonglong2 r = *reinterpret_cast<const ulonglong2*>(
                        &S.rec4[(bh * 4 + bb) * 16 + gg]);
                    fma2(ww[0 * 4 + bb], w0.x, r.x); fma2(ww[0 * 4 + bb], w0.y, r.y);
                    fma2(ww[1 * 4 + bb], w1.x, r.x); fma2(ww[1 * 4 + bb], w1.y, r.y);
                    fma2(ww[2 * 4 + bb], w2.x, r.x); fma2(ww[2 * 4 + bb], w2.y, r.y);
                    fma2(ww[3 * 4 + bb], w3.x, r.x); fma2(ww[3 * 4 + bb], w3.y, r.y);
                }
            }
            #pragma unroll
            for (int bb = 0; bb < 4; ++bb) {
                float4 o; float2 f;
                f = unpk(ww[0 * 4 + bb]); o.x = f.x + f.y;
                f = unpk(ww[1 * 4 + bb]); o.y = f.x + f.y;
                f = unpk(ww[2 * 4 + bb]); o.z = f.x + f.y;
                f = unpk(ww[3 * 4 + bb]); o.w = f.x + f.y;
                st_cluster_v4(wr_addr[bb], o);
            }
        }
        CLUSTER_SYNC();

        // ---- E: reduce wrecv, update hy/hz, store states, all-gather hy ----
        if (t < 128) {
            float4 w = *reinterpret_cast<const float4*>(&S.wrecv[(0 * 8 + ub) * 64 + uq * 4]);
            #pragma unroll
            for (int j = 1; j < CSZ; ++j) {
                float4 u = *reinterpret_cast<const float4*>(&S.wrecv[(j * 8 + ub) * 64 + uq * 4]);
                w.x += u.x; w.y += u.y; w.z += u.z; w.w += u.w;
            }
            float4 hy = *reinterpret_cast<const float4*>(&S.hy_s[ub * 64 + uq * 4]);
            float4 hz = *reinterpret_cast<const float4*>(&S.hz_s[ub * 64 + uq * 4]);
            float4 i2 = *reinterpret_cast<const float4*>(&S.i2h[ub * 64 + uq * 4]);
            float4 gm = *reinterpret_cast<const float4*>(&S.gammaS[uq * 4]);
            float4 ep = *reinterpret_cast<const float4*>(&S.epsS[uq * 4]);
            hz.x += DT_C * (i2.x - w.x - gm.x * hy.x - ep.x * hz.x);
            hz.y += DT_C * (i2.y - w.y - gm.y * hy.y - ep.y * hz.y);
            hz.z += DT_C * (i2.z - w.z - gm.z * hy.z - ep.z * hz.z);
            hz.w += DT_C * (i2.w - w.w - gm.w * hy.w - ep.w * hz.w);
            hy.x += DT_C * hz.x; hy.y += DT_C * hz.y;
            hy.z += DT_C * hz.z; hy.w += DT_C * hz.w;
            *reinterpret_cast<float4*>(&S.hy_s[ub * 64 + uq * 4]) = hy;
            *reinterpret_cast<float4*>(&S.hz_s[ub * 64 + uq * 4]) = hz;
            *reinterpret_cast<float4*>(
                outp + (((size_t)(cluster * BC + ub)) * SEQ + step) * N_HID + h0 + uq * 4) = hy;
            #pragma unroll
            for (uint32_t p = 0; p < CSZ; ++p) st_cluster_v4(hyb_addr[p], hy);
        }
        CLUSTER_SYNC();
    }

    // ---- final hy appended after states ----
    if (out_size >= BATCH * SEQ * N_HID + BATCH * N_HID && t < 128) {
        float4 hy = *reinterpret_cast<const float4*>(&S.hy_s[ub * 64 + uq * 4]);
        *reinterpret_cast<float4*>(
            outp + (size_t)BATCH * SEQ * N_HID +
            (size_t)(cluster * BC + ub) * N_HID + h0 + uq * 4) = hy;
    }
}

extern "C" void kernel_launch(void* const* d_in, const int* in_sizes, int n_in,
                              void* d_out, int out_size) {
    (void)in_sizes; (void)n_in;
    const float* x     = (const float*)d_in[0];
    const float* x2h   = (const float*)d_in[1];
    const float* h2h   = (const float*)d_in[2];
    const float* bias  = (const float*)d_in[3];
    const float* gamma = (const float*)d_in[4];
    const float* eps   = (const float*)d_in[5];
    float* out = (float*)d_out;

    const int pre_smem = (64 * 512 + 8 * 64 * 2) * 4;
    cudaFuncSetAttribute(i2h_kernel,
                         cudaFuncAttributeMaxDynamicSharedMemorySize, pre_smem);
    cudaFuncSetAttribute(piron_kernel,
                         cudaFuncAttributeMaxDynamicSharedMemorySize, (int)sizeof(Smem));

    // prelude: i2h_all = tanh(x @ x2h) written in place into out[:, t, :]
    i2h_kernel<<<PRE_CTAS, 256, pre_smem>>>(x, x2h, out);
    // main recurrence: 16 clusters x 8 CTAs
    piron_kernel<<<(BATCH / BC) * CSZ, THREADS, sizeof(Smem)>>>(
        h2h, bias, gamma, eps, out, out_size);
}